// round 12
// baseline (speedup 1.0000x reference)
#include <cuda_runtime.h>
#include <cstdint>
#include <math.h>

#define N_LEVELS 16
#define LOG2_T 19
#define TABLE_SIZE (1u << LOG2_T)
#define TABLE_MASK (TABLE_SIZE - 1u)

#define THREADS 256

struct ResParams { float resm1[N_LEVELS]; };

// Best structure (R11, 156.0us): 8 lanes per point, lane k handles levels
// 2k/2k+1, warp stores 512B contiguous (4 wf = floor), __stcs streaming
// stores. Cache policy by level hot-set size vs 228KB L1:
//   k==0 : levels 0,1  (32KB, 85KB)   -> both __ldg  (L1)
//   k==1 : level 2 (216KB) -> __ldg ; level 3 (592KB) -> __ldcg
//   k>=2 : levels 4..15 (>1.5MB each) -> __ldcg (L2-only, no L1 thrash)
__global__ void __launch_bounds__(THREADS) hashgrid_kernel(
    const float* __restrict__ x,
    const float2* __restrict__ tables,
    float4* __restrict__ out,
    int n, ResParams rp)
{
    const int tid = blockIdx.x * THREADS + threadIdx.x;
    const int p   = tid >> 3;       // point index
    const int k   = tid & 7;        // float4 slot within the output row
    if (p >= n) return;

    // 8 lanes share these addresses -> L1 broadcast, ~free.
    const float px = __ldg(&x[3 * p + 0]);
    const float py = __ldg(&x[3 * p + 1]);
    const float pz = __ldg(&x[3 * p + 2]);

    // Match reference: x_norm = (x + 1) / 2 in f32 (no FMA contraction)
    const float xn = __fmul_rn(__fadd_rn(px, 1.0f), 0.5f);
    const float yn = __fmul_rn(__fadd_rn(py, 1.0f), 0.5f);
    const float zn = __fmul_rn(__fadd_rn(pz, 1.0f), 0.5f);

    const int l0 = 2 * k;
    const int l1 = 2 * k + 1;

    const float r0 = rp.resm1[l0];
    const float r1 = rp.resm1[l1];

    // scaled = x_norm * (res - 1); truncating cast == floor (operands >= 0)
    const uint32_t gx0 = (uint32_t)__fmul_rn(xn, r0);
    const uint32_t gy0 = (uint32_t)__fmul_rn(yn, r0);
    const uint32_t gz0 = (uint32_t)__fmul_rn(zn, r0);
    const uint32_t gx1 = (uint32_t)__fmul_rn(xn, r1);
    const uint32_t gy1 = (uint32_t)__fmul_rn(yn, r1);
    const uint32_t gz1 = (uint32_t)__fmul_rn(zn, r1);

    const uint32_t h0 =
        (gx0 ^ (gy0 * 2654435761u) ^ (gz0 * 805459861u)) & TABLE_MASK;
    const uint32_t h1 =
        (gx1 ^ (gy1 * 2654435761u) ^ (gz1 * 805459861u)) & TABLE_MASK;

    const float2* a0 = &tables[(size_t)l0 * TABLE_SIZE + h0];
    const float2* a1 = &tables[(size_t)l1 * TABLE_SIZE + h1];

    // k uniform per thread: predicated LDGs, wavefront count unchanged.
    // First gather L1-cached for levels 0,1,2 (k<=1); second only for k==0.
    const float2 f0 = (k <= 1) ? __ldg(a0) : __ldcg(a0);
    const float2 f1 = (k == 0) ? __ldg(a1) : __ldcg(a1);

    // Evict-first store: output is write-once, never re-read.
    __stcs(&out[(size_t)tid], make_float4(f0.x, f0.y, f1.x, f1.y));
}

extern "C" void kernel_launch(void* const* d_in, const int* in_sizes, int n_in,
                              void* d_out, int out_size)
{
    const float*  x      = (const float*)d_in[0];
    const float2* tables = (const float2*)d_in[1];
    float4*       out    = (float4*)d_out;

    const int n = in_sizes[0] / 3;  // x has N*3 elements

    // Resolutions via the same double-precision libm chain as the Python
    // reference: b = exp((log(2048) - log(16)) / 15); res_l = int(16 * b**l).
    // Proven bit-identical (rel_err == 0.0) across all passing rounds.
    ResParams rp;
    {
        const double b = exp((log(2048.0) - log(16.0)) / 15.0);
        for (int l = 0; l < N_LEVELS; l++) {
            int res = (int)(16.0 * pow(b, (double)l));
            rp.resm1[l] = (float)res - 1.0f;
        }
    }

    const long long total = (long long)n * 8;            // one thread per float4
    const int blocks = (int)((total + THREADS - 1) / THREADS);
    hashgrid_kernel<<<blocks, THREADS>>>(x, tables, out, n, rp);
}

// round 13
// speedup vs baseline: 1.0544x; 1.0544x over previous
#include <cuda_runtime.h>
#include <cstdint>
#include <math.h>

#define N_LEVELS 16
#define LOG2_T 19
#define TABLE_SIZE (1u << LOG2_T)
#define TABLE_MASK (TABLE_SIZE - 1u)

#define THREADS 256

struct ResParams { float resm1[N_LEVELS]; };

// FINAL (R11, 156.0us best): 8 lanes per point, lane k handles levels
// 2k/2k+1, warp stores 512B contiguous (4 wf = floor), __stcs streaming
// stores. Mixed gather cache policy — levels 0-1 (lane k==0; hot sets
// 32KB+85KB fit the 228KB L1) keep L1 allocation (__ldg); levels >=2
// bypass L1 (__ldcg) so their miss streams don't thrash the coarse set.
// R12 measured that extending L1 caching to level 2 (216KB) regresses.
__global__ void __launch_bounds__(THREADS) hashgrid_kernel(
    const float* __restrict__ x,
    const float2* __restrict__ tables,
    float4* __restrict__ out,
    int n, ResParams rp)
{
    const int tid = blockIdx.x * THREADS + threadIdx.x;
    const int p   = tid >> 3;       // point index
    const int k   = tid & 7;        // float4 slot within the output row
    if (p >= n) return;

    // 8 lanes share these addresses -> L1 broadcast, ~free.
    const float px = __ldg(&x[3 * p + 0]);
    const float py = __ldg(&x[3 * p + 1]);
    const float pz = __ldg(&x[3 * p + 2]);

    // Match reference: x_norm = (x + 1) / 2 in f32 (no FMA contraction)
    const float xn = __fmul_rn(__fadd_rn(px, 1.0f), 0.5f);
    const float yn = __fmul_rn(__fadd_rn(py, 1.0f), 0.5f);
    const float zn = __fmul_rn(__fadd_rn(pz, 1.0f), 0.5f);

    const int l0 = 2 * k;
    const int l1 = 2 * k + 1;

    const float r0 = rp.resm1[l0];
    const float r1 = rp.resm1[l1];

    // scaled = x_norm * (res - 1); truncating cast == floor (operands >= 0)
    const uint32_t gx0 = (uint32_t)__fmul_rn(xn, r0);
    const uint32_t gy0 = (uint32_t)__fmul_rn(yn, r0);
    const uint32_t gz0 = (uint32_t)__fmul_rn(zn, r0);
    const uint32_t gx1 = (uint32_t)__fmul_rn(xn, r1);
    const uint32_t gy1 = (uint32_t)__fmul_rn(yn, r1);
    const uint32_t gz1 = (uint32_t)__fmul_rn(zn, r1);

    const uint32_t h0 =
        (gx0 ^ (gy0 * 2654435761u) ^ (gz0 * 805459861u)) & TABLE_MASK;
    const uint32_t h1 =
        (gx1 ^ (gy1 * 2654435761u) ^ (gz1 * 805459861u)) & TABLE_MASK;

    const float2* a0 = &tables[(size_t)l0 * TABLE_SIZE + h0];
    const float2* a1 = &tables[(size_t)l1 * TABLE_SIZE + h1];

    // k is uniform per thread: levels 0-1 (k==0) L1-cached, rest L2-only.
    // Compiles to predicated LDGs; wavefront count unchanged.
    const float2 f0 = (k == 0) ? __ldg(a0) : __ldcg(a0);
    const float2 f1 = (k == 0) ? __ldg(a1) : __ldcg(a1);

    // Evict-first store: output is write-once, never re-read.
    __stcs(&out[(size_t)tid], make_float4(f0.x, f0.y, f1.x, f1.y));
}

extern "C" void kernel_launch(void* const* d_in, const int* in_sizes, int n_in,
                              void* d_out, int out_size)
{
    const float*  x      = (const float*)d_in[0];
    const float2* tables = (const float2*)d_in[1];
    float4*       out    = (float4*)d_out;

    const int n = in_sizes[0] / 3;  // x has N*3 elements

    // Resolutions via the same double-precision libm chain as the Python
    // reference: b = exp((log(2048) - log(16)) / 15); res_l = int(16 * b**l).
    // Proven bit-identical (rel_err == 0.0) across all passing rounds.
    ResParams rp;
    {
        const double b = exp((log(2048.0) - log(16.0)) / 15.0);
        for (int l = 0; l < N_LEVELS; l++) {
            int res = (int)(16.0 * pow(b, (double)l));
            rp.resm1[l] = (float)res - 1.0f;
        }
    }

    const long long total = (long long)n * 8;            // one thread per float4
    const int blocks = (int)((total + THREADS - 1) / THREADS);
    hashgrid_kernel<<<blocks, THREADS>>>(x, tables, out, n, rp);
}